// round 1
// baseline (speedup 1.0000x reference)
#include <cuda_runtime.h>
#include <cstdint>

#define B_   2
#define C_   64
#define N_   9216
#define C8_  8
#define TK   64      // keys per smem tile
#define JT   128     // queries (j) per block
#define NSQ  14      // Gram-matrix squarings

// ---------------- scratch (device globals; no allocation allowed) ----------
__device__ float g_inv_sigma[3];
__device__ float g_fT[B_ * N_ * C8_];   // [b][n][8]   keys  (f)
__device__ float g_gT[B_ * N_ * C8_];   // [b][n][8]   queries (g)
__device__ float g_hT[B_ * N_ * C_];    // [b][n][64]  values (h)

// ---------------- f32x2 packed helpers (Blackwell sm_103a) -----------------
__device__ __forceinline__ unsigned long long pack2(float a, float b) {
    unsigned long long r;
    asm("mov.b64 %0, {%1, %2};" : "=l"(r) : "f"(a), "f"(b));
    return r;
}
__device__ __forceinline__ void unpack2(unsigned long long v, float &a, float &b) {
    asm("mov.b64 {%0, %1}, %2;" : "=f"(a), "=f"(b) : "l"(v));
}
__device__ __forceinline__ unsigned long long fma2(unsigned long long a,
                                                   unsigned long long b,
                                                   unsigned long long c) {
    unsigned long long d;
    asm("fma.rn.f32x2 %0, %1, %2, %3;" : "=l"(d) : "l"(a), "l"(b), "l"(c));
    return d;
}
__device__ __forceinline__ unsigned long long mul2(unsigned long long a,
                                                   unsigned long long b) {
    unsigned long long d;
    asm("mul.rn.f32x2 %0, %1, %2;" : "=l"(d) : "l"(a), "l"(b));
    return d;
}
__device__ __forceinline__ void cp_async16(uint32_t saddr, const void *gaddr) {
    asm volatile("cp.async.cg.shared.global [%0], [%1], 16;\n"
                 :: "r"(saddr), "l"(gaddr));
}

// ============================================================================
// Kernel 1: 1/sigma_max for Wq (8x64), Wk (8x64), Wv (64x64).
// G = W W^T (d x d). Repeatedly square G with Frobenius normalization:
// M -> (M M)/||M M||_F. After NSQ squarings M ∝ v1 v1^T. Take the column with
// the largest diagonal as v1, then lambda = ||W^T v||^2 / ||v||^2 (exact
// Rayleigh quotient against the original W).
// ============================================================================
__global__ void sigma_kernel(const float *__restrict__ Wq,
                             const float *__restrict__ Wk,
                             const float *__restrict__ Wv) {
    __shared__ float Ms[64 * 64];
    __shared__ float Ts[64 * 64];
    __shared__ float red[256];
    __shared__ float s_scale;
    __shared__ int   s_jmax;

    const int mat = blockIdx.x;
    const float *W = (mat == 0) ? Wq : (mat == 1) ? Wk : Wv;
    const int d = (mat == 2) ? 64 : 8;
    const int tid = threadIdx.x;

    // Build G = W W^T
    for (int e = tid; e < d * d; e += 256) {
        int i = e / d, j = e % d;
        float s = 0.f;
        #pragma unroll 8
        for (int k = 0; k < 64; k++) s += W[i * 64 + k] * W[j * 64 + k];
        Ms[e] = s;
    }
    __syncthreads();

    for (int it = 0; it < NSQ; ++it) {
        for (int e = tid; e < d * d; e += 256) {
            int i = e / d, j = e % d;
            float s = 0.f;
            for (int k = 0; k < d; k++) s += Ms[i * d + k] * Ms[k * d + j];
            Ts[e] = s;
        }
        __syncthreads();
        float part = 0.f;
        for (int e = tid; e < d * d; e += 256) part += Ts[e] * Ts[e];
        red[tid] = part;
        __syncthreads();
        for (int off = 128; off; off >>= 1) {
            if (tid < off) red[tid] += red[tid + off];
            __syncthreads();
        }
        if (tid == 0) s_scale = rsqrtf(red[0]);
        __syncthreads();
        float sc = s_scale;
        for (int e = tid; e < d * d; e += 256) Ms[e] = Ts[e] * sc;
        __syncthreads();
    }

    if (tid == 0) {
        int jm = 0; float best = Ms[0];
        for (int j = 1; j < d; j++) {
            float v = Ms[j * d + j];
            if (v > best) { best = v; jm = j; }
        }
        s_jmax = jm;
    }
    __syncthreads();
    const int jm = s_jmax;

    // num = ||W^T v||^2
    float part = 0.f;
    if (tid < 64) {
        float y = 0.f;
        for (int i = 0; i < d; i++) y += W[i * 64 + tid] * Ms[i * d + jm];
        part = y * y;
    }
    red[tid] = (tid < 64) ? part : 0.f;
    __syncthreads();
    for (int off = 128; off; off >>= 1) {
        if (tid < off) red[tid] += red[tid + off];
        __syncthreads();
    }
    float num = red[0];
    __syncthreads();
    // den = ||v||^2
    float p2 = 0.f;
    if (tid < d) { float v = Ms[tid * d + jm]; p2 = v * v; }
    red[tid] = (tid < d) ? p2 : 0.f;
    __syncthreads();
    for (int off = 128; off; off >>= 1) {
        if (tid < off) red[tid] += red[tid + off];
        __syncthreads();
    }
    if (tid == 0) {
        float den = red[0];
        g_inv_sigma[mat] = rsqrtf(num / den);   // 1/sigma = lambda^(-1/2)
    }
}

// ============================================================================
// Kernel 2: f/g/h projections, transposed layouts.
//   fT[b][n][o] = (Wq/sq) x[b][:,n] + bq        (o < 8)
//   gT[b][n][o] = (Wk/sk) x[b][:,n] + bk        (o < 8)
//   hT[b][n][o] = (Wv/sv) x[b][:,n] + bv        (o < 64)
// Block = 128 consecutive n (coalesced x loads); transposed, pre-scaled
// weights in smem (broadcast LDS.128 per c).
// ============================================================================
__global__ void __launch_bounds__(128)
fgh_kernel(const float *__restrict__ x,
           const float *__restrict__ Wq, const float *__restrict__ bq,
           const float *__restrict__ Wk, const float *__restrict__ bk,
           const float *__restrict__ Wv, const float *__restrict__ bv) {
    __shared__ float WvT[64 * 64];              // [c][o], scaled by 1/sv
    __shared__ float WqT[64 * 8];               // [c][o], scaled by 1/sq
    __shared__ float WkT[64 * 8];               // [c][o], scaled by 1/sk
    const int tid = threadIdx.x;
    const float isq = g_inv_sigma[0];
    const float isk = g_inv_sigma[1];
    const float isv = g_inv_sigma[2];
    for (int e = tid; e < 64 * 64; e += 128) {
        int o = e / 64, c = e % 64;
        WvT[c * 64 + o] = Wv[e] * isv;
    }
    for (int e = tid; e < 8 * 64; e += 128) {
        int o = e / 64, c = e % 64;
        WqT[c * 8 + o] = Wq[e] * isq;
        WkT[c * 8 + o] = Wk[e] * isk;
    }
    __syncthreads();

    const int b = blockIdx.y;
    const int n = blockIdx.x * 128 + tid;
    const float *xp = x + (size_t)b * C_ * N_ + n;

    float h[64], f[8], g[8];
    #pragma unroll
    for (int k = 0; k < 64; k++) h[k] = 0.f;
    #pragma unroll
    for (int k = 0; k < 8; k++) { f[k] = 0.f; g[k] = 0.f; }

    for (int c = 0; c < 64; c++) {
        float xv = xp[(size_t)c * N_];
        const float4 *wv4 = (const float4 *)&WvT[c * 64];
        #pragma unroll
        for (int k = 0; k < 16; k++) {
            float4 w = wv4[k];
            h[4 * k + 0] = fmaf(w.x, xv, h[4 * k + 0]);
            h[4 * k + 1] = fmaf(w.y, xv, h[4 * k + 1]);
            h[4 * k + 2] = fmaf(w.z, xv, h[4 * k + 2]);
            h[4 * k + 3] = fmaf(w.w, xv, h[4 * k + 3]);
        }
        const float4 *wq4 = (const float4 *)&WqT[c * 8];
        const float4 *wk4 = (const float4 *)&WkT[c * 8];
        #pragma unroll
        for (int k = 0; k < 2; k++) {
            float4 wa = wq4[k];
            f[4 * k + 0] = fmaf(wa.x, xv, f[4 * k + 0]);
            f[4 * k + 1] = fmaf(wa.y, xv, f[4 * k + 1]);
            f[4 * k + 2] = fmaf(wa.z, xv, f[4 * k + 2]);
            f[4 * k + 3] = fmaf(wa.w, xv, f[4 * k + 3]);
            float4 wb = wk4[k];
            g[4 * k + 0] = fmaf(wb.x, xv, g[4 * k + 0]);
            g[4 * k + 1] = fmaf(wb.y, xv, g[4 * k + 1]);
            g[4 * k + 2] = fmaf(wb.z, xv, g[4 * k + 2]);
            g[4 * k + 3] = fmaf(wb.w, xv, g[4 * k + 3]);
        }
    }
    #pragma unroll
    for (int k = 0; k < 8; k++) { f[k] += bq[k]; g[k] += bk[k]; }
    #pragma unroll
    for (int k = 0; k < 64; k++) h[k] += bv[k];

    float4 *fo = (float4 *)&g_fT[(size_t)(b * N_ + n) * 8];
    float4 *go = (float4 *)&g_gT[(size_t)(b * N_ + n) * 8];
    fo[0] = make_float4(f[0], f[1], f[2], f[3]);
    fo[1] = make_float4(f[4], f[5], f[6], f[7]);
    go[0] = make_float4(g[0], g[1], g[2], g[3]);
    go[1] = make_float4(g[4], g[5], g[6], g[7]);
    float4 *ho = (float4 *)&g_hT[(size_t)(b * N_ + n) * 64];
    #pragma unroll
    for (int k = 0; k < 16; k++)
        ho[k] = make_float4(h[4 * k], h[4 * k + 1], h[4 * k + 2], h[4 * k + 3]);
}

// ============================================================================
// Kernel 3: fused flash attention.
// Per thread: one output column j. Stream key tiles (TK keys) through
// double-buffered smem via cp.async. Online softmax over keys; 64-channel
// accumulator in 32 packed f32x2 registers (fma.rn.f32x2).
// Epilogue: o[c][j] = gamma * acc[c]/l + x[c][j].
// ============================================================================
__global__ void __launch_bounds__(JT)
attn_kernel(const float *__restrict__ x,
            const float *__restrict__ gamma,
            float *__restrict__ out) {
    __shared__ float sf[2][TK * 8];
    __shared__ float sh[2][TK * 64];

    const int tid = threadIdx.x;
    const int b = blockIdx.y;
    const int j = blockIdx.x * JT + tid;

    // query vector g_j (8 floats)
    const float4 *gp = (const float4 *)&g_gT[(size_t)(b * N_ + j) * 8];
    const float4 q0 = gp[0], q1 = gp[1];

    const float4 *fg = (const float4 *)&g_fT[(size_t)b * N_ * 8];
    const float4 *hg = (const float4 *)&g_hT[(size_t)b * N_ * 64];

    uint32_t sf_s[2], sh_s[2];
    sf_s[0] = (uint32_t)__cvta_generic_to_shared(&sf[0][0]);
    sf_s[1] = (uint32_t)__cvta_generic_to_shared(&sf[1][0]);
    sh_s[0] = (uint32_t)__cvta_generic_to_shared(&sh[0][0]);
    sh_s[1] = (uint32_t)__cvta_generic_to_shared(&sh[1][0]);

    auto load_tile = [&](int t, int buf) {
        // f tile: TK*8 floats = 128 float4, 1 per thread
        cp_async16(sf_s[buf] + tid * 16, fg + t * (TK * 8 / 4) + tid);
        // h tile: TK*64 floats = 1024 float4, 8 per thread
        const float4 *src = hg + t * (TK * 64 / 4);
        #pragma unroll
        for (int r = 0; r < 8; r++)
            cp_async16(sh_s[buf] + (r * 128 + tid) * 16, src + r * 128 + tid);
    };

    unsigned long long acc[32];
    #pragma unroll
    for (int k = 0; k < 32; k++) acc[k] = 0ull;
    float m = -3.0e38f;
    float l = 0.f;

    load_tile(0, 0);
    asm volatile("cp.async.commit_group;\n");

    const int NT = N_ / TK;   // 144
    for (int t = 0; t < NT; t++) {
        const int buf = t & 1;
        if (t + 1 < NT) {
            load_tile(t + 1, buf ^ 1);
            asm volatile("cp.async.commit_group;\n");
            asm volatile("cp.async.wait_group 1;\n");
        } else {
            asm volatile("cp.async.wait_group 0;\n");
        }
        __syncthreads();

        const float4 *f4 = (const float4 *)&sf[buf][0];
        const ulonglong2 *h2b = (const ulonglong2 *)&sh[buf][0];

        #pragma unroll 4
        for (int u = 0; u < TK; u++) {
            float4 fa = f4[2 * u], fb = f4[2 * u + 1];
            float s = fa.x * q0.x + fa.y * q0.y + fa.z * q0.z + fa.w * q0.w +
                      fb.x * q1.x + fb.y * q1.y + fb.z * q1.z + fb.w * q1.w;
            if (s > m) {                       // rare (~ln N record maxes)
                float corr = __expf(m - s);
                l *= corr;
                unsigned long long cc = pack2(corr, corr);
                #pragma unroll
                for (int k = 0; k < 32; k++) acc[k] = mul2(acc[k], cc);
                m = s;
            }
            float p = __expf(s - m);
            l += p;
            unsigned long long pp = pack2(p, p);
            const ulonglong2 *hrow = h2b + u * 16;   // 64 floats = 16x 16B
            #pragma unroll
            for (int k = 0; k < 16; k++) {
                ulonglong2 hv = hrow[k];
                acc[2 * k]     = fma2(pp, hv.x, acc[2 * k]);
                acc[2 * k + 1] = fma2(pp, hv.y, acc[2 * k + 1]);
            }
        }
        __syncthreads();
    }

    // epilogue: out[b][c][j] = gamma * acc[c]/l + x[b][c][j]
    const float gscale = gamma[0] / l;
    const float *xp = x + (size_t)b * C_ * N_ + j;
    float *op = out + (size_t)b * C_ * N_ + j;
    #pragma unroll
    for (int k = 0; k < 32; k++) {
        float lo, hi;
        unpack2(acc[k], lo, hi);
        op[(size_t)(2 * k) * N_]     = fmaf(gscale, lo, xp[(size_t)(2 * k) * N_]);
        op[(size_t)(2 * k + 1) * N_] = fmaf(gscale, hi, xp[(size_t)(2 * k + 1) * N_]);
    }
}

// ============================================================================
extern "C" void kernel_launch(void *const *d_in, const int *in_sizes, int n_in,
                              void *d_out, int out_size) {
    const float *x     = (const float *)d_in[0];
    const float *Wq    = (const float *)d_in[1];
    const float *bq    = (const float *)d_in[2];
    const float *Wk    = (const float *)d_in[3];
    const float *bk    = (const float *)d_in[4];
    const float *Wv    = (const float *)d_in[5];
    const float *bv    = (const float *)d_in[6];
    const float *gamma = (const float *)d_in[7];
    float *out = (float *)d_out;

    sigma_kernel<<<3, 256>>>(Wq, Wk, Wv);
    fgh_kernel<<<dim3(N_ / 128, B_), 128>>>(x, Wq, bq, Wk, bk, Wv, bv);
    attn_kernel<<<dim3(N_ / JT, B_), JT>>>(x, gamma, out);
}

// round 12
// speedup vs baseline: 1.4979x; 1.4979x over previous
#include <cuda_runtime.h>
#include <cstdint>

#define B_   2
#define C_   64
#define N_   9216
#define C8_  8
#define JT   128     // queries (j) per block
#define SPL  4       // key splits per block
#define TK   16      // keys per smem tile
#define KPS  (N_ / SPL)        // 2304 keys per split
#define NTIL (KPS / TK)        // 144 tiles per split
#define NPI  240     // power iterations for sigma

// ---------------- scratch (device globals; no allocation allowed) ----------
__device__ float g_inv_sigma[3];
__device__ float g_fT[B_ * N_ * C8_];   // [b][n][8]   keys  (f)
__device__ float g_gT[B_ * N_ * C8_];   // [b][n][8]   queries (g)
__device__ float g_hT[B_ * N_ * C_];    // [b][n][64]  values (h)

// ---------------- f32x2 packed helpers (Blackwell sm_103a) -----------------
__device__ __forceinline__ unsigned long long pack2(float a, float b) {
    unsigned long long r;
    asm("mov.b64 %0, {%1, %2};" : "=l"(r) : "f"(a), "f"(b));
    return r;
}
__device__ __forceinline__ void unpack2(unsigned long long v, float &a, float &b) {
    asm("mov.b64 {%0, %1}, %2;" : "=f"(a), "=f"(b) : "l"(v));
}
__device__ __forceinline__ unsigned long long fma2(unsigned long long a,
                                                   unsigned long long b,
                                                   unsigned long long c) {
    unsigned long long d;
    asm("fma.rn.f32x2 %0, %1, %2, %3;" : "=l"(d) : "l"(a), "l"(b), "l"(c));
    return d;
}
__device__ __forceinline__ unsigned long long mul2(unsigned long long a,
                                                   unsigned long long b) {
    unsigned long long d;
    asm("mul.rn.f32x2 %0, %1, %2;" : "=l"(d) : "l"(a), "l"(b));
    return d;
}
__device__ __forceinline__ void cp_async16(uint32_t saddr, const void *gaddr) {
    asm volatile("cp.async.cg.shared.global [%0], [%1], 16;\n"
                 :: "r"(saddr), "l"(gaddr));
}
__device__ __forceinline__ void bar_named(int id, int cnt) {
    asm volatile("bar.sync %0, %1;" :: "r"(id), "r"(cnt) : "memory");
}

// ============================================================================
// Kernel 1 (v2): 1/sigma_max via power iteration on G = W W^T.
// Quartered matvec with 256 threads; normalize every 16 iters; final
// Rayleigh quotient lambda = ||W^T v||^2 / ||v||^2 against original W.
// ============================================================================
__global__ void __launch_bounds__(256)
sigma_kernel(const float *__restrict__ Wq,
             const float *__restrict__ Wk,
             const float *__restrict__ Wv) {
    __shared__ float Ws[64 * 64];       // W rows (row i = W[i][0..63])
    __shared__ float G[64 * 65];        // padded, conflict-free
    __shared__ float v[2][64];
    __shared__ float red[256];
    __shared__ float s_scale;

    const int mat = blockIdx.x;
    const float *W = (mat == 0) ? Wq : (mat == 1) ? Wk : Wv;
    const int d = (mat == 2) ? 64 : 8;
    const int tid = threadIdx.x;
    const int i = tid & 63;
    const int q = tid >> 6;

    for (int e = tid; e < d * 64; e += 256) Ws[e] = W[e];
    __syncthreads();

    // G = W W^T
    for (int e = tid; e < d * d; e += 256) {
        int r = e / d, c = e % d;
        float s = 0.f;
        #pragma unroll 8
        for (int k = 0; k < 64; k++) s += Ws[r * 64 + k] * Ws[c * 64 + k];
        G[r * 65 + c] = s;
    }
    __syncthreads();

    // v0 = G * ones
    if (tid < d) {
        float s = 0.f;
        for (int c = 0; c < d; c++) s += G[tid * 65 + c];
        v[0][tid] = s;
    }
    __syncthreads();

    int cur = 0;
    const int dq = d >> 2;              // chunk per quarter
    for (int it = 0; it < NPI; it++) {
        float s = 0.f;
        if (i < d) {
            const int k0 = q * dq;
            #pragma unroll 4
            for (int k = k0; k < k0 + dq; k++) s += G[i * 65 + k] * v[cur][k];
        }
        red[tid] = s;
        __syncthreads();
        if (tid < d)
            v[cur ^ 1][tid] = red[tid] + red[tid + 64] + red[tid + 128] + red[tid + 192];
        cur ^= 1;
        __syncthreads();
        if ((it & 15) == 15) {
            float p = (tid < d) ? v[cur][tid] * v[cur][tid] : 0.f;
            red[tid] = p;
            __syncthreads();
            for (int off = 128; off; off >>= 1) {
                if (tid < off) red[tid] += red[tid + off];
                __syncthreads();
            }
            if (tid == 0) s_scale = rsqrtf(red[0]);
            __syncthreads();
            if (tid < d) v[cur][tid] *= s_scale;
            __syncthreads();
        }
    }

    // Rayleigh: y = W^T v ; lambda = ||y||^2 / ||v||^2
    float yk = 0.f;
    if (tid < 64) {
        for (int r = 0; r < d; r++) yk += Ws[r * 64 + tid] * v[cur][r];
    }
    red[tid] = (tid < 64) ? yk * yk : 0.f;
    __syncthreads();
    for (int off = 128; off; off >>= 1) {
        if (tid < off) red[tid] += red[tid + off];
        __syncthreads();
    }
    float num = red[0];
    __syncthreads();
    red[tid] = (tid < d) ? v[cur][tid] * v[cur][tid] : 0.f;
    __syncthreads();
    for (int off = 128; off; off >>= 1) {
        if (tid < off) red[tid] += red[tid + off];
        __syncthreads();
    }
    if (tid == 0) g_inv_sigma[mat] = rsqrtf(num / red[0]);
}

// ============================================================================
// Kernel 2: f/g/h projections, transposed outputs, f32x2 accumulation.
// ============================================================================
__global__ void __launch_bounds__(128)
fgh_kernel(const float *__restrict__ x,
           const float *__restrict__ Wq, const float *__restrict__ bq,
           const float *__restrict__ Wk, const float *__restrict__ bk,
           const float *__restrict__ Wv, const float *__restrict__ bv) {
    __shared__ float WvT[64 * 64];              // [c][o], scaled by 1/sv
    __shared__ float WqT[64 * 8];               // [c][o], scaled by 1/sq
    __shared__ float WkT[64 * 8];               // [c][o], scaled by 1/sk
    const int tid = threadIdx.x;
    const float isq = g_inv_sigma[0];
    const float isk = g_inv_sigma[1];
    const float isv = g_inv_sigma[2];
    for (int e = tid; e < 64 * 64; e += 128) {
        int o = e / 64, c = e % 64;
        WvT[c * 64 + o] = Wv[e] * isv;
    }
    for (int e = tid; e < 8 * 64; e += 128) {
        int o = e / 64, c = e % 64;
        WqT[c * 8 + o] = Wq[e] * isq;
        WkT[c * 8 + o] = Wk[e] * isk;
    }
    __syncthreads();

    const int b = blockIdx.y;
    const int n = blockIdx.x * 128 + tid;
    const float *xp = x + (size_t)b * C_ * N_ + n;

    unsigned long long h2[32], f2[4], g2[4];
    #pragma unroll
    for (int k = 0; k < 32; k++) h2[k] = 0ull;
    #pragma unroll
    for (int k = 0; k < 4; k++) { f2[k] = 0ull; g2[k] = 0ull; }

    for (int c = 0; c < 64; c++) {
        float xv = xp[(size_t)c * N_];
        unsigned long long xx = pack2(xv, xv);
        const ulonglong2 *wv2 = (const ulonglong2 *)&WvT[c * 64];
        #pragma unroll
        for (int k = 0; k < 16; k++) {
            ulonglong2 w = wv2[k];
            h2[2 * k]     = fma2(xx, w.x, h2[2 * k]);
            h2[2 * k + 1] = fma2(xx, w.y, h2[2 * k + 1]);
        }
        const ulonglong2 *wq2 = (const ulonglong2 *)&WqT[c * 8];
        const ulonglong2 *wk2 = (const ulonglong2 *)&WkT[c * 8];
        #pragma unroll
        for (int k = 0; k < 2; k++) {
            ulonglong2 wa = wq2[k];
            f2[2 * k]     = fma2(xx, wa.x, f2[2 * k]);
            f2[2 * k + 1] = fma2(xx, wa.y, f2[2 * k + 1]);
            ulonglong2 wb = wk2[k];
            g2[2 * k]     = fma2(xx, wb.x, g2[2 * k]);
            g2[2 * k + 1] = fma2(xx, wb.y, g2[2 * k + 1]);
        }
    }

    float f[8], g[8];
    #pragma unroll
    for (int k = 0; k < 4; k++) {
        unpack2(f2[k], f[2 * k], f[2 * k + 1]);
        unpack2(g2[k], g[2 * k], g[2 * k + 1]);
    }
    #pragma unroll
    for (int k = 0; k < 8; k++) { f[k] += bq[k]; g[k] += bk[k]; }

    float4 *fo = (float4 *)&g_fT[(size_t)(b * N_ + n) * 8];
    float4 *go = (float4 *)&g_gT[(size_t)(b * N_ + n) * 8];
    fo[0] = make_float4(f[0], f[1], f[2], f[3]);
    fo[1] = make_float4(f[4], f[5], f[6], f[7]);
    go[0] = make_float4(g[0], g[1], g[2], g[3]);
    go[1] = make_float4(g[4], g[5], g[6], g[7]);

    float4 *ho = (float4 *)&g_hT[(size_t)(b * N_ + n) * 64];
    #pragma unroll
    for (int k = 0; k < 16; k++) {
        float a0, a1, a2, a3;
        unpack2(h2[2 * k], a0, a1);
        unpack2(h2[2 * k + 1], a2, a3);
        ho[k] = make_float4(a0 + bv[4 * k], a1 + bv[4 * k + 1],
                            a2 + bv[4 * k + 2], a3 + bv[4 * k + 3]);
    }
}

// ============================================================================
// Kernel 3 (v2): fused flash attention, 4-way key split per block.
// 512 threads = 4 splits x 128 j. Each split streams its N/4 keys through
// its own double-buffered smem tiles (named barriers), then exact merge.
// ============================================================================
// smem layout (floats):
#define SF_OFF(s, buf)  (((s) * 2 + (buf)) * (TK * 8))                 // [0,1024)
#define SH_OFF(s, buf)  (1024 + ((s) * 2 + (buf)) * (TK * 64))        // [1024,9216)
#define MM_OFF          0        // m_buf[4][128]  (overlaps sf, after sync)
#define LL_OFF          512      // l_buf[4][128]
#define MACC_OFF        1024     // macc[128][65]  (overlaps sh, after sync)
#define SMEM_FLOATS     (1024 + 128 * 65)

__global__ void __launch_bounds__(SPL * JT, 1)
attn_kernel(const float *__restrict__ x,
            const float *__restrict__ gamma,
            float *__restrict__ out) {
    __shared__ float sm[SMEM_FLOATS];

    const int tid = threadIdx.x;
    const int jl  = tid & (JT - 1);
    const int s   = tid >> 7;           // split id 0..3
    const int b   = blockIdx.y;
    const int j   = blockIdx.x * JT + jl;

    // query vector g_j (8 floats)
    const float4 *gp = (const float4 *)&g_gT[(size_t)(b * N_ + j) * 8];
    const float4 q0 = gp[0], q1 = gp[1];

    const float4 *fg = (const float4 *)&g_fT[((size_t)b * N_ + (size_t)s * KPS) * 8];
    const float4 *hg = (const float4 *)&g_hT[((size_t)b * N_ + (size_t)s * KPS) * 64];

    const uint32_t smem_u = (uint32_t)__cvta_generic_to_shared(sm);

    auto load_tile = [&](int t, int buf) {
        // f tile: TK*8 floats = 32 float4 -> threads jl<32 load 1 each
        if (jl < TK * 2) {
            cp_async16(smem_u + (SF_OFF(s, buf) + jl * 4) * 4,
                       fg + (size_t)t * (TK * 2) + jl);
        }
        // h tile: TK*64 floats = 256 float4 -> 2 per thread, coalesced
        const float4 *src = hg + (size_t)t * (TK * 16);
        #pragma unroll
        for (int r = 0; r < 2; r++) {
            int idx = r * JT + jl;
            cp_async16(smem_u + (SH_OFF(s, buf) + idx * 4) * 4, src + idx);
        }
        asm volatile("cp.async.commit_group;\n");
    };

    unsigned long long acc[32];
    #pragma unroll
    for (int k = 0; k < 32; k++) acc[k] = 0ull;
    float m = -3.0e38f;
    float l = 0.f;

    load_tile(0, 0);

    for (int t = 0; t < NTIL; t++) {
        const int buf = t & 1;
        if (t + 1 < NTIL) {
            load_tile(t + 1, buf ^ 1);
            asm volatile("cp.async.wait_group 1;\n");
        } else {
            asm volatile("cp.async.wait_group 0;\n");
        }
        bar_named(1 + s, JT);           // tile visible to whole split

        const float4 *f4 = (const float4 *)&sm[SF_OFF(s, buf)];
        const ulonglong2 *h2b = (const ulonglong2 *)&sm[SH_OFF(s, buf)];

        #pragma unroll 4
        for (int u = 0; u < TK; u++) {
            float4 fa = f4[2 * u], fb = f4[2 * u + 1];
            float sc = fa.x * q0.x + fa.y * q0.y + fa.z * q0.z + fa.w * q0.w +
                       fb.x * q1.x + fb.y * q1.y + fb.z * q1.z + fb.w * q1.w;
            if (sc > m) {                       // rare record maxes
                float corr = __expf(m - sc);
                l *= corr;
                unsigned long long cc = pack2(corr, corr);
                #pragma unroll
                for (int k = 0; k < 32; k++) acc[k] = mul2(acc[k], cc);
                m = sc;
            }
            float p = __expf(sc - m);
            l += p;
            unsigned long long pp = pack2(p, p);
            const ulonglong2 *hrow = h2b + u * 16;   // 64 floats
            #pragma unroll
            for (int k = 0; k < 16; k++) {
                ulonglong2 hv = hrow[k];
                acc[2 * k]     = fma2(pp, hv.x, acc[2 * k]);
                acc[2 * k + 1] = fma2(pp, hv.y, acc[2 * k + 1]);
            }
        }
        bar_named(1 + s, JT);           // split done reading buf
    }

    // ---------------- merge across splits ----------------
    __syncthreads();                    // all splits done; tile smem is dead
    sm[MM_OFF + s * JT + jl] = m;
    sm[LL_OFF + s * JT + jl] = l;
    __syncthreads();

    float M = sm[MM_OFF + jl];
    #pragma unroll
    for (int s2 = 1; s2 < SPL; s2++) M = fmaxf(M, sm[MM_OFF + s2 * JT + jl]);
    float L = 0.f;
    #pragma unroll
    for (int s2 = 0; s2 < SPL; s2++)
        L += sm[LL_OFF + s2 * JT + jl] * __expf(sm[MM_OFF + s2 * JT + jl] - M);
    const float es = __expf(m - M);

    // phased accumulation into macc[jl][65]
    #pragma unroll
    for (int p = 0; p < SPL; p++) {
        if (s == p) {
            float *mrow = &sm[MACC_OFF + jl * 65];
            #pragma unroll
            for (int k = 0; k < 32; k++) {
                float a0, a1;
                unpack2(acc[k], a0, a1);
                if (p == 0) {
                    mrow[2 * k]     = es * a0;
                    mrow[2 * k + 1] = es * a1;
                } else {
                    mrow[2 * k]     += es * a0;
                    mrow[2 * k + 1] += es * a1;
                }
            }
        }
        __syncthreads();
    }

    // ---------------- epilogue ----------------
    const float gs = gamma[0] / L;
    const int cb = s;                   // reuse split id as channel base
    const float *xp = x + (size_t)b * C_ * N_ + j;
    float *op = out + (size_t)b * C_ * N_ + j;
    const float *mrow = &sm[MACC_OFF + jl * 65];
    #pragma unroll
    for (int cc = 0; cc < 16; cc++) {
        int c = cc * 4 + cb;
        op[(size_t)c * N_] = fmaf(gs, mrow[c], xp[(size_t)c * N_]);
    }
}

// ============================================================================
extern "C" void kernel_launch(void *const *d_in, const int *in_sizes, int n_in,
                              void *d_out, int out_size) {
    const float *x     = (const float *)d_in[0];
    const float *Wq    = (const float *)d_in[1];
    const float *bq    = (const float *)d_in[2];
    const float *Wk    = (const float *)d_in[3];
    const float *bk    = (const float *)d_in[4];
    const float *Wv    = (const float *)d_in[5];
    const float *bv    = (const float *)d_in[6];
    const float *gamma = (const float *)d_in[7];
    float *out = (float *)d_out;

    sigma_kernel<<<3, 256>>>(Wq, Wk, Wv);
    fgh_kernel<<<dim3(N_ / 128, B_), 128>>>(x, Wq, bq, Wk, bk, Wv, bv);
    attn_kernel<<<dim3(N_ / JT, B_), SPL * JT>>>(x, gamma, out);
}